// round 16
// baseline (speedup 1.0000x reference)
#include <cuda_runtime.h>
#include <cuda_fp16.h>
#include <math.h>

#define HW 65536
#define BRS (4 * 16 * HW)   // per-branch output stride (4,194,304 elements)

// ---------------- device scratch (no allocation allowed) -------------------
__device__ float  g_x   [4 * 16 * HW];  // in_conv output     [b][c][h][w]
__device__ float  g_c   [4 * (4 * 16 * HW)]; // per-branch conv [br][b][c][h][w]
__device__ __half g_brh [4 * BRS];      // branch outputs     [br][b][c][w][h] (half)
__device__ float  g_mask[4 * HW];       // sigmoid mask       [b][w][h]
__device__ float  g_k3  [256 * 8];      // softmax(scales2)
__device__ float  g_k4  [256];          // softmax(scales3)  [g][e]
__device__ float  g_s1  [4];            // softmax(scales1)

// ---------------------------------------------------------------------------
__global__ void prep_kernel(const float* __restrict__ s1,
                            const float* __restrict__ s2,
                            const float* __restrict__ s3) {
    int t = threadIdx.x;  // 256 threads
    {
        const float* row = s2 + t * 8;
        float m = row[0];
        #pragma unroll
        for (int j = 1; j < 8; ++j) m = fmaxf(m, row[j]);
        float e[8], sum = 0.f;
        #pragma unroll
        for (int j = 0; j < 8; ++j) { e[j] = expf(row[j] - m); sum += e[j]; }
        float iv = 1.f / sum;
        #pragma unroll
        for (int j = 0; j < 8; ++j) g_k3[t * 8 + j] = e[j] * iv;
    }
    if (t < 16) {
        const float* row = s3 + t * 16;
        float m = row[0];
        #pragma unroll
        for (int j = 1; j < 16; ++j) m = fmaxf(m, row[j]);
        float e[16], sum = 0.f;
        #pragma unroll
        for (int j = 0; j < 16; ++j) { e[j] = expf(row[j] - m); sum += e[j]; }
        float iv = 1.f / sum;
        #pragma unroll
        for (int j = 0; j < 16; ++j) g_k4[t * 16 + j] = e[j] * iv;
    }
    if (t == 0) {
        float m = fmaxf(fmaxf(s1[0], s1[1]), fmaxf(s1[2], s1[3]));
        float e0 = expf(s1[0] - m), e1 = expf(s1[1] - m);
        float e2 = expf(s1[2] - m), e3 = expf(s1[3] - m);
        float iv = 1.f / (e0 + e1 + e2 + e3);
        g_s1[0] = e0 * iv; g_s1[1] = e1 * iv; g_s1[2] = e2 * iv; g_s1[3] = e3 * iv;
    }
}

// ---------------------------------------------------------------------------
// 1x1 conv 64 -> 16 (+bias): one thread per pixel, 16 outputs.
__global__ void in_conv(const float* __restrict__ cen,
                        const float* __restrict__ w,
                        const float* __restrict__ bias) {
    __shared__ float sw[1024];
    __shared__ float sb[16];
    int tid = threadIdx.x;
    for (int i = tid; i < 1024; i += 256) sw[i] = w[i];
    if (tid < 16) sb[tid] = bias[tid];
    __syncthreads();
    int idx = blockIdx.x * 256 + tid;          // 0 .. 262143
    int b = idx >> 16, p = idx & 65535;
    float acc[16];
    #pragma unroll
    for (int c = 0; c < 16; ++c) acc[c] = sb[c];
    const float* cp = cen + (size_t)b * 64 * HW + p;
    #pragma unroll 4
    for (int ci = 0; ci < 64; ++ci) {
        float v = cp[(size_t)ci * HW];
        #pragma unroll
        for (int c = 0; c < 16; ++c) acc[c] = fmaf(sw[c * 64 + ci], v, acc[c]);
    }
    float* xp = g_x + (size_t)b * 16 * HW + p;
    #pragma unroll
    for (int c = 0; c < 16; ++c) xp[(size_t)c * HW] = acc[c];
}

// ---------------------------------------------------------------------------
// KxK conv body (templated), writing to g_c plane for branch br.
template <int K>
__device__ __forceinline__ void mid_body(const float* __restrict__ w,
                                         const float* __restrict__ bias,
                                         float* tile,   // [(16+2P)][(32+2P)+1]
                                         float* ws,     // [16*K*K]
                                         int bx, int br) {
    constexpr int P  = (K - 1) / 2;
    constexpr int TW = 32 + 2 * P;
    constexpr int TH = 16 + 2 * P;
    constexpr int TWP = TW + 1;
    int b  = blockIdx.z;
    int h0 = blockIdx.y * 16, w0 = bx * 32;
    int tx = threadIdx.x & 31, ty = threadIdx.x >> 5;
    int tid = threadIdx.x;
    float acc[16][2];
    #pragma unroll
    for (int co = 0; co < 16; ++co) {
        float bv = __ldg(bias + co);
        acc[co][0] = bv; acc[co][1] = bv;
    }
    for (int ci = 0; ci < 16; ++ci) {
        __syncthreads();
        for (int i = tid; i < 16 * K * K; i += 256) {
            int co = i / (K * K), rc = i % (K * K);
            ws[i] = w[(co * 16 + ci) * K * K + rc];
        }
        const float* xp = g_x + (size_t)(b * 16 + ci) * HW;
        for (int i = tid; i < TH * TW; i += 256) {
            int th = i / TW, tw = i - th * TW;
            int hh = h0 + th - P, wv = w0 + tw - P;
            tile[th * TWP + tw] = ((unsigned)hh < 256u && (unsigned)wv < 256u)
                                      ? xp[hh * 256 + wv] : 0.f;
        }
        __syncthreads();
        #pragma unroll
        for (int r = 0; r < K; ++r)
            #pragma unroll
            for (int c = 0; c < K; ++c) {
                float v0 = tile[(ty + r) * TWP + tx + c];
                float v1 = tile[(ty + 8 + r) * TWP + tx + c];
                #pragma unroll
                for (int co = 0; co < 16; ++co) {
                    float wv = ws[co * K * K + r * K + c];
                    acc[co][0] = fmaf(wv, v0, acc[co][0]);
                    acc[co][1] = fmaf(wv, v1, acc[co][1]);
                }
            }
    }
    #pragma unroll
    for (int co = 0; co < 16; ++co) {
        float* op = g_c + (size_t)br * (4 * 16 * HW)
                  + (size_t)(b * 16 + co) * HW + (h0 + ty) * 256 + w0 + tx;
        op[0]       = acc[co][0];
        op[8 * 256] = acc[co][1];
    }
}

// One launch for all four mid convs. grid(32, 16, 4): bx = x & 7, br = x >> 3.
__global__ void __launch_bounds__(256) mid_all(
    const float* w0_, const float* b0_, const float* w1_, const float* b1_,
    const float* w2_, const float* b2_, const float* w3_, const float* b3_) {
    __shared__ float tile[30 * 47];   // K=7: TH=30, TW+1=47
    __shared__ float ws[16 * 49];
    int br = blockIdx.x >> 3;
    int bx = blockIdx.x & 7;
    switch (br) {
        case 0: mid_body<1>(w0_, b0_, tile, ws, bx, 0); break;
        case 1: mid_body<3>(w1_, b1_, tile, ws, bx, 1); break;
        case 2: mid_body<5>(w2_, b2_, tile, ws, bx, 2); break;
        default: mid_body<7>(w3_, b3_, tile, ws, bx, 3); break;
    }
}

// ---------------------------------------------------------------------------
// bit-cast helpers for shfl on __half2 (pure register reinterpretation)
__device__ __forceinline__ unsigned h2_as_u32(__half2 h) {
    return *reinterpret_cast<unsigned*>(&h);
}
__device__ __forceinline__ __half2 u32_as_h2(unsigned u) {
    return *reinterpret_cast<__half2*>(&u);
}

// ---------------------------------------------------------------------------
// Packed fp16x2 dual sign-flip bitonic sort (two interleaved packed arrays =
// four channels per call). Layout i = lane*8 + r, ascending per half.
__device__ __forceinline__ void cmpA2(__half2& a, __half2& b) {
    __half2 mn = __hmin2(a, b), mx = __hmax2(a, b); a = mn; b = mx;
}
__device__ __forceinline__ void batcher8x2h(__half2 s[8], __half2 t[8]) {
    cmpA2(s[0], s[1]); cmpA2(t[0], t[1]); cmpA2(s[2], s[3]); cmpA2(t[2], t[3]);
    cmpA2(s[4], s[5]); cmpA2(t[4], t[5]); cmpA2(s[6], s[7]); cmpA2(t[6], t[7]);
    cmpA2(s[0], s[2]); cmpA2(t[0], t[2]); cmpA2(s[1], s[3]); cmpA2(t[1], t[3]);
    cmpA2(s[4], s[6]); cmpA2(t[4], t[6]); cmpA2(s[5], s[7]); cmpA2(t[5], t[7]);
    cmpA2(s[1], s[2]); cmpA2(t[1], t[2]); cmpA2(s[5], s[6]); cmpA2(t[5], t[6]);
    cmpA2(s[0], s[4]); cmpA2(t[0], t[4]); cmpA2(s[2], s[6]); cmpA2(t[2], t[6]);
    cmpA2(s[1], s[5]); cmpA2(t[1], t[5]); cmpA2(s[3], s[7]); cmpA2(t[3], t[7]);
    cmpA2(s[2], s[4]); cmpA2(t[2], t[4]); cmpA2(s[3], s[5]); cmpA2(t[3], t[5]);
    cmpA2(s[1], s[2]); cmpA2(t[1], t[2]); cmpA2(s[3], s[4]); cmpA2(t[3], t[4]);
    cmpA2(s[5], s[6]); cmpA2(t[5], t[6]);
}
__device__ __forceinline__ void inreg3x2h(__half2 s[8], __half2 t[8]) {
    cmpA2(s[0], s[4]); cmpA2(t[0], t[4]); cmpA2(s[1], s[5]); cmpA2(t[1], t[5]);
    cmpA2(s[2], s[6]); cmpA2(t[2], t[6]); cmpA2(s[3], s[7]); cmpA2(t[3], t[7]);
    cmpA2(s[0], s[2]); cmpA2(t[0], t[2]); cmpA2(s[1], s[3]); cmpA2(t[1], t[3]);
    cmpA2(s[4], s[6]); cmpA2(t[4], t[6]); cmpA2(s[5], s[7]); cmpA2(t[5], t[7]);
    cmpA2(s[0], s[1]); cmpA2(t[0], t[1]); cmpA2(s[2], s[3]); cmpA2(t[2], t[3]);
    cmpA2(s[4], s[5]); cmpA2(t[4], t[5]); cmpA2(s[6], s[7]); cmpA2(t[6], t[7]);
}
__device__ __forceinline__ void negif2h(__half2 s[8], __half2 t[8], int f) {
    __half2 sg = f ? __float2half2_rn(-1.f) : __float2half2_rn(1.f);
    #pragma unroll
    for (int r = 0; r < 8; ++r) { s[r] = __hmul2(s[r], sg); t[r] = __hmul2(t[r], sg); }
}
template <int M>
__device__ __forceinline__ void shufstage2h(__half2 s[8], __half2 t[8], bool keepmin) {
    #pragma unroll
    for (int r = 0; r < 8; ++r) {
        unsigned o1 = __shfl_xor_sync(0xffffffffu, h2_as_u32(s[r]), M);
        unsigned o2 = __shfl_xor_sync(0xffffffffu, h2_as_u32(t[r]), M);
        __half2 v1 = u32_as_h2(o1);
        __half2 v2 = u32_as_h2(o2);
        s[r] = keepmin ? __hmin2(s[r], v1) : __hmax2(s[r], v1);
        t[r] = keepmin ? __hmin2(t[r], v2) : __hmax2(t[r], v2);
    }
}
__device__ __forceinline__ void sort256x2h(__half2 s[8], __half2 t[8], int lane) {
    int b0 = lane & 1, b1 = (lane >> 1) & 1, b2 = (lane >> 2) & 1;
    int b3 = (lane >> 3) & 1, b4 = (lane >> 4) & 1;
    bool k1 = (lane & 1) == 0, k2 = (lane & 2) == 0, k4 = (lane & 4) == 0;
    bool k8 = (lane & 8) == 0, k16 = (lane & 16) == 0;
    negif2h(s, t, b0);
    batcher8x2h(s, t);
    negif2h(s, t, b0 ^ b1);
    shufstage2h<1>(s, t, k1);
    inreg3x2h(s, t);
    negif2h(s, t, b1 ^ b2);
    shufstage2h<2>(s, t, k2);
    shufstage2h<1>(s, t, k1);
    inreg3x2h(s, t);
    negif2h(s, t, b2 ^ b3);
    shufstage2h<4>(s, t, k4);
    shufstage2h<2>(s, t, k2);
    shufstage2h<1>(s, t, k1);
    inreg3x2h(s, t);
    negif2h(s, t, b3 ^ b4);
    shufstage2h<8>(s, t, k8);
    shufstage2h<4>(s, t, k4);
    shufstage2h<2>(s, t, k2);
    shufstage2h<1>(s, t, k1);
    inreg3x2h(s, t);
    negif2h(s, t, b4);
    shufstage2h<16>(s, t, k16);
    shufstage2h<8>(s, t, k8);
    shufstage2h<4>(s, t, k4);
    shufstage2h<2>(s, t, k2);
    shufstage2h<1>(s, t, k1);
    inreg3x2h(s, t);
}

// ---------------------------------------------------------------------------
// Fused branch body (templated on S), operating on dynamic smem column buffer.
template <int S>
__device__ __forceinline__ void fused_body(float* cs, __half2* k3h, float* k4s,
                                           int bx, int br) {
    constexpr int NC = 8 + 2 * S;
    constexpr int CP = 289;
    int b = blockIdx.z, g = blockIdx.y, w0 = bx * 8;
    int tid  = threadIdx.x;
    int lane = tid & 31, warp = tid >> 5;

    if (tid < 64) {
        int p = tid >> 3, d = tid & 7;
        int row = g * 16 + 2 * p;
        k3h[tid] = __floats2half2_rn(g_k3[row * 8 + d], g_k3[(row + 1) * 8 + d]);
    }
    if (tid < 16) k4s[tid] = g_k4[g * 16 + tid];

    const float* cbase = g_c + (size_t)br * (4 * 16 * HW) + (size_t)(b * 16 + g) * HW;
    #pragma unroll 1
    for (int j = tid; j < NC * 256; j += 256) {
        int h   = j / NC;
        int col = j - h * NC;
        int wg  = w0 - S + col;
        float v = 0.f;
        if ((unsigned)wg < 256u) v = cbase[h * 256 + wg];
        cs[col * CP + h + (h >> 3)] = v;
    }
    __syncthreads();

    int colc = warp + S;
    const float* pC = cs + colc * CP;
    const float* pL = cs + (colc - S) * CP;
    const float* pR = cs + (colc + S) * CP;

    __half2 Lh[8], Ch[8], Rh[8];
    float acc[8];
    #pragma unroll
    for (int r = 0; r < 8; ++r) {
        int h  = lane * 8 + r;
        int ai = h + (h >> 3);
        Lh[r] = __float2half2_rn(pL[ai]);
        Ch[r] = __float2half2_rn(pC[ai]);
        Rh[r] = __float2half2_rn(pR[ai]);
        acc[r] = 0.f;
    }

    #pragma unroll 1
    for (int ep = 0; ep < 4; ++ep) {
        __half2 whA[8], whB[8];
        #pragma unroll
        for (int d = 0; d < 8; ++d) {
            whA[d] = k3h[(2 * ep)     * 8 + d];
            whB[d] = k3h[(2 * ep + 1) * 8 + d];
        }

        __half2 s[8], t[8];
        #pragma unroll
        for (int r = 0; r < 8; ++r) {
            __half2 luh, cuh, ruh, ldh, cdh, rdh;
            if (r >= S) {
                luh = Lh[r - S]; cuh = Ch[r - S]; ruh = Rh[r - S];
            } else {
                int hm  = lane * 8 + r - S;
                bool vm = hm >= 0;
                int hmc = vm ? hm : 0;
                int aim = hmc + (hmc >> 3);
                luh = __float2half2_rn(vm ? pL[aim] : 0.f);
                cuh = __float2half2_rn(vm ? pC[aim] : 0.f);
                ruh = __float2half2_rn(vm ? pR[aim] : 0.f);
            }
            if (r + S < 8) {
                ldh = Lh[r + S]; cdh = Ch[r + S]; rdh = Rh[r + S];
            } else {
                int hp  = lane * 8 + r + S;
                bool vp = hp < 256;
                int hpc = vp ? hp : 255;
                int aip = hpc + (hpc >> 3);
                ldh = __float2half2_rn(vp ? pL[aip] : 0.f);
                cdh = __float2half2_rn(vp ? pC[aip] : 0.f);
                rdh = __float2half2_rn(vp ? pR[aip] : 0.f);
            }
            __half2 cch = Ch[r], Lrh = Lh[r], Rrh = Rh[r];

            __half2 A0 = __hmul2(luh, whA[0]);
            A0 = __hfma2(cuh, whA[1], A0); A0 = __hfma2(ruh, whA[2], A0);
            A0 = __hfma2(Lrh, whA[3], A0); A0 = __hfma2(rdh, whA[4], A0);
            A0 = __hfma2(cdh, whA[5], A0); A0 = __hfma2(ldh, whA[6], A0);
            A0 = __hfma2(Rrh, whA[7], A0);
            __half2 B0 = __hmul2(rdh, whA[0]);
            B0 = __hfma2(cdh, whA[1], B0); B0 = __hfma2(ldh, whA[2], B0);
            B0 = __hfma2(Rrh, whA[3], B0); B0 = __hfma2(luh, whA[4], B0);
            B0 = __hfma2(cuh, whA[5], B0); B0 = __hfma2(ruh, whA[6], B0);
            B0 = __hfma2(Lrh, whA[7], B0);
            s[r] = __hmul2(__hsub2(cch, A0), __hsub2(cch, B0));

            __half2 A1 = __hmul2(luh, whB[0]);
            A1 = __hfma2(cuh, whB[1], A1); A1 = __hfma2(ruh, whB[2], A1);
            A1 = __hfma2(Lrh, whB[3], A1); A1 = __hfma2(rdh, whB[4], A1);
            A1 = __hfma2(cdh, whB[5], A1); A1 = __hfma2(ldh, whB[6], A1);
            A1 = __hfma2(Rrh, whB[7], A1);
            __half2 B1 = __hmul2(rdh, whB[0]);
            B1 = __hfma2(cdh, whB[1], B1); B1 = __hfma2(ldh, whB[2], B1);
            B1 = __hfma2(Rrh, whB[3], B1); B1 = __hfma2(luh, whB[4], B1);
            B1 = __hfma2(cuh, whB[5], B1); B1 = __hfma2(ruh, whB[6], B1);
            B1 = __hfma2(Lrh, whB[7], B1);
            t[r] = __hmul2(__hsub2(cch, A1), __hsub2(cch, B1));
        }

        sort256x2h(s, t, lane);

        int e0 = 4 * ep;
        float k40 = k4s[e0 + 0], k41 = k4s[e0 + 1];
        float k42 = k4s[e0 + 2], k43 = k4s[e0 + 3];
        #pragma unroll
        for (int r = 0; r < 8; ++r) {
            float v0 = __low2float(s[r]),  v1 = __high2float(s[r]);
            float v2 = __low2float(t[r]),  v3 = __high2float(t[r]);
            float g0 = 1.f / (1.f + __expf(-v0));
            float g1 = 1.f / (1.f + __expf(-v1));
            float g2 = 1.f / (1.f + __expf(-v2));
            float g3 = 1.f / (1.f + __expf(-v3));
            float a = acc[r];
            a = fmaf(k40 * v0, g0, a);
            a = fmaf(k41 * v1, g1, a);
            a = fmaf(k42 * v2, g2, a);
            a = fmaf(k43 * v3, g3, a);
            acc[r] = a;
        }
    }

    int w = w0 + warp;
    __half* op = g_brh + (size_t)br * BRS + ((size_t)((b * 16 + g) * 256 + w)) * 256;
    __half2 o[4];
    o[0] = __floats2half2_rn(acc[0], acc[1]);
    o[1] = __floats2half2_rn(acc[2], acc[3]);
    o[2] = __floats2half2_rn(acc[4], acc[5]);
    o[3] = __floats2half2_rn(acc[6], acc[7]);
    *reinterpret_cast<uint4*>(op + lane * 8) = *reinterpret_cast<uint4*>(o);
}

// One launch for all four branches. grid(128, 16, 4): bx = x & 31, br = x >> 5.
// Dynamic smem = S=7 column buffer (22 * 289 floats).
__global__ void __launch_bounds__(256, 3) fused_all() {
    extern __shared__ float cs[];
    __shared__ __half2 k3h[64];
    __shared__ float k4s[16];
    int br = blockIdx.x >> 5;
    int bx = blockIdx.x & 31;
    switch (br) {
        case 0: fused_body<1>(cs, k3h, k4s, bx, 0); break;
        case 1: fused_body<3>(cs, k3h, k4s, bx, 1); break;
        case 2: fused_body<5>(cs, k3h, k4s, bx, 2); break;
        default: fused_body<7>(cs, k3h, k4s, bx, 3); break;
    }
}

// ---------------------------------------------------------------------------
// 3x3 conv on transposed layout with on-the-fly branch combine (max + mean of
// 4 half branch planes) + BN(eval) + SiLU + 1x1 -> sigmoid mask.
__global__ void post_conv(const float* __restrict__ wb,
                          const float* __restrict__ gamma,
                          const float* __restrict__ beta,
                          const float* __restrict__ mean,
                          const float* __restrict__ var,
                          const float* __restrict__ wout,
                          const float* __restrict__ bout) {
    __shared__ float tile[18][35];
    __shared__ float ws[16 * 9];
    int b  = blockIdx.z;
    int o0 = blockIdx.y * 16, i0 = blockIdx.x * 32;
    int tx = threadIdx.x, ty = threadIdx.y;
    int tid = ty * 32 + tx;
    float acc[16][2];
    #pragma unroll
    for (int co = 0; co < 16; ++co) { acc[co][0] = 0.f; acc[co][1] = 0.f; }
    for (int ci = 0; ci < 16; ++ci) {
        __syncthreads();
        for (int i = tid; i < 144; i += 256) {
            int co = i / 9, rc = i % 9;
            int bi = rc / 3, ao = rc % 3;
            ws[co * 9 + ao * 3 + bi] = wb[(co * 16 + ci) * 9 + bi * 3 + ao];
        }
        size_t plane = (size_t)(b * 16 + ci) * HW;
        for (int i = tid; i < 18 * 34; i += 256) {
            int to = i / 34, ti = i - to * 34;
            int oo = o0 + to - 1, ii = i0 + ti - 1;
            float v = 0.f;
            if ((unsigned)oo < 256u && (unsigned)ii < 256u) {
                size_t off = plane + oo * 256 + ii;
                float v0 = __half2float(g_brh[off]);
                float v1 = __half2float(g_brh[BRS + off]);
                float v2 = __half2float(g_brh[2 * (size_t)BRS + off]);
                float v3 = __half2float(g_brh[3 * (size_t)BRS + off]);
                v = fmaxf(fmaxf(v0, v1), fmaxf(v2, v3))
                    + 0.25f * (v0 + v1 + v2 + v3);
            }
            tile[to][ti] = v;
        }
        __syncthreads();
        #pragma unroll
        for (int a = 0; a < 3; ++a)
            #pragma unroll
            for (int bb = 0; bb < 3; ++bb) {
                float v0 = tile[ty + a][tx + bb];
                float v1 = tile[ty + 8 + a][tx + bb];
                #pragma unroll
                for (int co = 0; co < 16; ++co) {
                    float wv = ws[co * 9 + a * 3 + bb];
                    acc[co][0] = fmaf(wv, v0, acc[co][0]);
                    acc[co][1] = fmaf(wv, v1, acc[co][1]);
                }
            }
    }
    float m0 = 0.f, m1 = 0.f;
    #pragma unroll
    for (int co = 0; co < 16; ++co) {
        float sc = __ldg(gamma + co) * rsqrtf(__ldg(var + co) + 1e-5f);
        float sh = __ldg(beta + co) - __ldg(mean + co) * sc;
        float h0 = acc[co][0] * sc + sh;
        float h1 = acc[co][1] * sc + sh;
        h0 = h0 / (1.f + __expf(-h0));
        h1 = h1 / (1.f + __expf(-h1));
        float wv = __ldg(wout + co);
        m0 = fmaf(wv, h0, m0);
        m1 = fmaf(wv, h1, m1);
    }
    float bo = __ldg(bout);
    m0 = 1.f / (1.f + __expf(-(m0 + bo)));
    m1 = 1.f / (1.f + __expf(-(m1 + bo)));
    float* mp = g_mask + (size_t)b * HW + (o0 + ty) * 256 + i0 + tx;
    mp[0]       = m0;
    mp[8 * 256] = m1;
}

// ---------------------------------------------------------------------------
// Final: out = cen * (mask*m*s0 + m*s1 + s2*mask + s3), mask stored [b][w][h].
__global__ void final_kernel(const float* __restrict__ cen,
                             const float* __restrict__ mas,
                             float* __restrict__ out) {
    __shared__ float mt[1024];              // [w][hoff] for this block's 4 rows
    int b  = blockIdx.y;
    int h0 = blockIdx.x * 4;
    int tid = threadIdx.x;
    #pragma unroll
    for (int i = tid; i < 1024; i += 256) {
        int wv = i >> 2, hoff = i & 3;
        mt[i] = g_mask[(size_t)b * HW + wv * 256 + h0 + hoff];
    }
    __syncthreads();
    float s0 = g_s1[0], s1 = g_s1[1], s2 = g_s1[2], s3 = g_s1[3];
    int hoff = tid >> 6;
    int h    = h0 + hoff;
    int wb4  = (tid & 63) * 4;
    float4 msv = *reinterpret_cast<const float4*>(
        mas + (size_t)b * HW + h * 256 + wb4);
    float coef[4];
    {
        float msa[4] = {msv.x, msv.y, msv.z, msv.w};
        #pragma unroll
        for (int j = 0; j < 4; ++j) {
            float mv = mt[(wb4 + j) * 4 + hoff];
            float m  = 1.f / (1.f + __expf(-msa[j]));
            coef[j] = m * fmaf(mv, s0, s1) + fmaf(s2, mv, s3);
        }
    }
    size_t base = (size_t)b * 64 * HW + (size_t)h * 256 + wb4;
    #pragma unroll 4
    for (int c = 0; c < 64; ++c) {
        size_t o = base + (size_t)c * HW;
        float4 cv = *reinterpret_cast<const float4*>(cen + o);
        cv.x *= coef[0]; cv.y *= coef[1]; cv.z *= coef[2]; cv.w *= coef[3];
        *reinterpret_cast<float4*>(out + o) = cv;
    }
}

// ---------------------------------------------------------------------------
extern "C" void kernel_launch(void* const* d_in, const int* in_sizes, int n_in,
                              void* d_out, int out_size) {
    const float* cen      = (const float*)d_in[0];
    const float* mas      = (const float*)d_in[1];
    const float* w_in     = (const float*)d_in[2];
    const float* b_in     = (const float*)d_in[3];
    const float* w_c0     = (const float*)d_in[4];
    const float* b_c0     = (const float*)d_in[5];
    const float* w_c1     = (const float*)d_in[6];
    const float* b_c1     = (const float*)d_in[7];
    const float* w_c2     = (const float*)d_in[8];
    const float* b_c2     = (const float*)d_in[9];
    const float* w_c3     = (const float*)d_in[10];
    const float* b_c3     = (const float*)d_in[11];
    const float* scales1  = (const float*)d_in[12];
    const float* scales2  = (const float*)d_in[13];
    const float* scales3  = (const float*)d_in[14];
    const float* w_base   = (const float*)d_in[15];
    const float* bn_gamma = (const float*)d_in[16];
    const float* bn_beta  = (const float*)d_in[17];
    const float* bn_mean  = (const float*)d_in[18];
    const float* bn_var   = (const float*)d_in[19];
    const float* w_out    = (const float*)d_in[20];
    const float* b_out    = (const float*)d_in[21];
    float* out = (float*)d_out;

    prep_kernel<<<1, 256>>>(scales1, scales2, scales3);
    in_conv<<<1024, 256>>>(cen, w_in, b_in);

    mid_all<<<dim3(32, 16, 4), 256>>>(w_c0, b_c0, w_c1, b_c1,
                                      w_c2, b_c2, w_c3, b_c3);

    int fsmem = 22 * 289 * sizeof(float);   // S=7 column buffer
    fused_all<<<dim3(128, 16, 4), 256, fsmem>>>();

    dim3 cgrid(8, 16, 4), cblk(32, 8);
    post_conv<<<cgrid, cblk>>>(w_base, bn_gamma, bn_beta, bn_mean, bn_var,
                               w_out, b_out);

    final_kernel<<<dim3(64, 4), 256>>>(cen, mas, out);
}

// round 17
// speedup vs baseline: 1.0845x; 1.0845x over previous
#include <cuda_runtime.h>
#include <cuda_fp16.h>
#include <math.h>

#define HW 65536
#define BRS (4 * 16 * HW)   // per-branch output stride (4,194,304 elements)

// ---------------- device scratch (no allocation allowed) -------------------
__device__ float  g_x   [4 * 16 * HW];  // in_conv output     [b][c][h][w]
__device__ float  g_c   [4 * (4 * 16 * HW)]; // per-branch conv [br][b][c][h][w]
__device__ __half g_brh [4 * BRS];      // branch outputs     [br][b][c][w][h] (half)
__device__ float  g_mask[4 * HW];       // sigmoid mask       [b][w][h]
__device__ float  g_k3  [256 * 8];      // softmax(scales2)
__device__ float  g_k4  [256];          // softmax(scales3)  [g][e]
__device__ float  g_s1  [4];            // softmax(scales1)

// ---------------------------------------------------------------------------
__global__ void prep_kernel(const float* __restrict__ s1,
                            const float* __restrict__ s2,
                            const float* __restrict__ s3) {
    int t = threadIdx.x;  // 256 threads
    {
        const float* row = s2 + t * 8;
        float m = row[0];
        #pragma unroll
        for (int j = 1; j < 8; ++j) m = fmaxf(m, row[j]);
        float e[8], sum = 0.f;
        #pragma unroll
        for (int j = 0; j < 8; ++j) { e[j] = expf(row[j] - m); sum += e[j]; }
        float iv = 1.f / sum;
        #pragma unroll
        for (int j = 0; j < 8; ++j) g_k3[t * 8 + j] = e[j] * iv;
    }
    if (t < 16) {
        const float* row = s3 + t * 16;
        float m = row[0];
        #pragma unroll
        for (int j = 1; j < 16; ++j) m = fmaxf(m, row[j]);
        float e[16], sum = 0.f;
        #pragma unroll
        for (int j = 0; j < 16; ++j) { e[j] = expf(row[j] - m); sum += e[j]; }
        float iv = 1.f / sum;
        #pragma unroll
        for (int j = 0; j < 16; ++j) g_k4[t * 16 + j] = e[j] * iv;
    }
    if (t == 0) {
        float m = fmaxf(fmaxf(s1[0], s1[1]), fmaxf(s1[2], s1[3]));
        float e0 = expf(s1[0] - m), e1 = expf(s1[1] - m);
        float e2 = expf(s1[2] - m), e3 = expf(s1[3] - m);
        float iv = 1.f / (e0 + e1 + e2 + e3);
        g_s1[0] = e0 * iv; g_s1[1] = e1 * iv; g_s1[2] = e2 * iv; g_s1[3] = e3 * iv;
    }
}

// ---------------------------------------------------------------------------
// 1x1 conv 64 -> 16 (+bias): one thread per pixel, 16 outputs.
__global__ void in_conv(const float* __restrict__ cen,
                        const float* __restrict__ w,
                        const float* __restrict__ bias) {
    __shared__ float sw[1024];
    __shared__ float sb[16];
    int tid = threadIdx.x;
    for (int i = tid; i < 1024; i += 256) sw[i] = w[i];
    if (tid < 16) sb[tid] = bias[tid];
    __syncthreads();
    int idx = blockIdx.x * 256 + tid;          // 0 .. 262143
    int b = idx >> 16, p = idx & 65535;
    float acc[16];
    #pragma unroll
    for (int c = 0; c < 16; ++c) acc[c] = sb[c];
    const float* cp = cen + (size_t)b * 64 * HW + p;
    #pragma unroll 4
    for (int ci = 0; ci < 64; ++ci) {
        float v = cp[(size_t)ci * HW];
        #pragma unroll
        for (int c = 0; c < 16; ++c) acc[c] = fmaf(sw[c * 64 + ci], v, acc[c]);
    }
    float* xp = g_x + (size_t)b * 16 * HW + p;
    #pragma unroll
    for (int c = 0; c < 16; ++c) xp[(size_t)c * HW] = acc[c];
}

// ---------------------------------------------------------------------------
// KxK conv body (templated), writing to g_c plane for branch br.
template <int K>
__device__ __forceinline__ void mid_body(const float* __restrict__ w,
                                         const float* __restrict__ bias,
                                         float* tile,   // [(16+2P)][(32+2P)+1]
                                         float* ws,     // [16*K*K]
                                         int bx, int br) {
    constexpr int P  = (K - 1) / 2;
    constexpr int TW = 32 + 2 * P;
    constexpr int TH = 16 + 2 * P;
    constexpr int TWP = TW + 1;
    int b  = blockIdx.z;
    int h0 = blockIdx.y * 16, w0 = bx * 32;
    int tx = threadIdx.x & 31, ty = threadIdx.x >> 5;
    int tid = threadIdx.x;
    float acc[16][2];
    #pragma unroll
    for (int co = 0; co < 16; ++co) {
        float bv = __ldg(bias + co);
        acc[co][0] = bv; acc[co][1] = bv;
    }
    for (int ci = 0; ci < 16; ++ci) {
        __syncthreads();
        for (int i = tid; i < 16 * K * K; i += 256) {
            int co = i / (K * K), rc = i % (K * K);
            ws[i] = w[(co * 16 + ci) * K * K + rc];
        }
        const float* xp = g_x + (size_t)(b * 16 + ci) * HW;
        for (int i = tid; i < TH * TW; i += 256) {
            int th = i / TW, tw = i - th * TW;
            int hh = h0 + th - P, wv = w0 + tw - P;
            tile[th * TWP + tw] = ((unsigned)hh < 256u && (unsigned)wv < 256u)
                                      ? xp[hh * 256 + wv] : 0.f;
        }
        __syncthreads();
        #pragma unroll
        for (int r = 0; r < K; ++r)
            #pragma unroll
            for (int c = 0; c < K; ++c) {
                float v0 = tile[(ty + r) * TWP + tx + c];
                float v1 = tile[(ty + 8 + r) * TWP + tx + c];
                #pragma unroll
                for (int co = 0; co < 16; ++co) {
                    float wv = ws[co * K * K + r * K + c];
                    acc[co][0] = fmaf(wv, v0, acc[co][0]);
                    acc[co][1] = fmaf(wv, v1, acc[co][1]);
                }
            }
    }
    #pragma unroll
    for (int co = 0; co < 16; ++co) {
        float* op = g_c + (size_t)br * (4 * 16 * HW)
                  + (size_t)(b * 16 + co) * HW + (h0 + ty) * 256 + w0 + tx;
        op[0]       = acc[co][0];
        op[8 * 256] = acc[co][1];
    }
}

// One launch for all four mid convs. grid(32, 16, 4): bx = x & 7, br = x >> 3.
__global__ void __launch_bounds__(256) mid_all(
    const float* w0_, const float* b0_, const float* w1_, const float* b1_,
    const float* w2_, const float* b2_, const float* w3_, const float* b3_) {
    __shared__ float tile[30 * 47];   // K=7: TH=30, TW+1=47
    __shared__ float ws[16 * 49];
    int br = blockIdx.x >> 3;
    int bx = blockIdx.x & 7;
    switch (br) {
        case 0: mid_body<1>(w0_, b0_, tile, ws, bx, 0); break;
        case 1: mid_body<3>(w1_, b1_, tile, ws, bx, 1); break;
        case 2: mid_body<5>(w2_, b2_, tile, ws, bx, 2); break;
        default: mid_body<7>(w3_, b3_, tile, ws, bx, 3); break;
    }
}

// ---------------------------------------------------------------------------
// bit-cast helpers for shfl on __half2 (pure register reinterpretation)
__device__ __forceinline__ unsigned h2_as_u32(__half2 h) {
    return *reinterpret_cast<unsigned*>(&h);
}
__device__ __forceinline__ __half2 u32_as_h2(unsigned u) {
    return *reinterpret_cast<__half2*>(&u);
}

// ---------------------------------------------------------------------------
// Packed fp16x2 dual sign-flip bitonic sort (two interleaved packed arrays =
// four channels per call). Layout i = lane*8 + r, ascending per half.
__device__ __forceinline__ void cmpA2(__half2& a, __half2& b) {
    __half2 mn = __hmin2(a, b), mx = __hmax2(a, b); a = mn; b = mx;
}
__device__ __forceinline__ void batcher8x2h(__half2 s[8], __half2 t[8]) {
    cmpA2(s[0], s[1]); cmpA2(t[0], t[1]); cmpA2(s[2], s[3]); cmpA2(t[2], t[3]);
    cmpA2(s[4], s[5]); cmpA2(t[4], t[5]); cmpA2(s[6], s[7]); cmpA2(t[6], t[7]);
    cmpA2(s[0], s[2]); cmpA2(t[0], t[2]); cmpA2(s[1], s[3]); cmpA2(t[1], t[3]);
    cmpA2(s[4], s[6]); cmpA2(t[4], t[6]); cmpA2(s[5], s[7]); cmpA2(t[5], t[7]);
    cmpA2(s[1], s[2]); cmpA2(t[1], t[2]); cmpA2(s[5], s[6]); cmpA2(t[5], t[6]);
    cmpA2(s[0], s[4]); cmpA2(t[0], t[4]); cmpA2(s[2], s[6]); cmpA2(t[2], t[6]);
    cmpA2(s[1], s[5]); cmpA2(t[1], t[5]); cmpA2(s[3], s[7]); cmpA2(t[3], t[7]);
    cmpA2(s[2], s[4]); cmpA2(t[2], t[4]); cmpA2(s[3], s[5]); cmpA2(t[3], t[5]);
    cmpA2(s[1], s[2]); cmpA2(t[1], t[2]); cmpA2(s[3], s[4]); cmpA2(t[3], t[4]);
    cmpA2(s[5], s[6]); cmpA2(t[5], t[6]);
}
__device__ __forceinline__ void inreg3x2h(__half2 s[8], __half2 t[8]) {
    cmpA2(s[0], s[4]); cmpA2(t[0], t[4]); cmpA2(s[1], s[5]); cmpA2(t[1], t[5]);
    cmpA2(s[2], s[6]); cmpA2(t[2], t[6]); cmpA2(s[3], s[7]); cmpA2(t[3], t[7]);
    cmpA2(s[0], s[2]); cmpA2(t[0], t[2]); cmpA2(s[1], s[3]); cmpA2(t[1], t[3]);
    cmpA2(s[4], s[6]); cmpA2(t[4], t[6]); cmpA2(s[5], s[7]); cmpA2(t[5], t[7]);
    cmpA2(s[0], s[1]); cmpA2(t[0], t[1]); cmpA2(s[2], s[3]); cmpA2(t[2], t[3]);
    cmpA2(s[4], s[5]); cmpA2(t[4], t[5]); cmpA2(s[6], s[7]); cmpA2(t[6], t[7]);
}
__device__ __forceinline__ void negif2h(__half2 s[8], __half2 t[8], int f) {
    __half2 sg = f ? __float2half2_rn(-1.f) : __float2half2_rn(1.f);
    #pragma unroll
    for (int r = 0; r < 8; ++r) { s[r] = __hmul2(s[r], sg); t[r] = __hmul2(t[r], sg); }
}
template <int M>
__device__ __forceinline__ void shufstage2h(__half2 s[8], __half2 t[8], bool keepmin) {
    #pragma unroll
    for (int r = 0; r < 8; ++r) {
        unsigned o1 = __shfl_xor_sync(0xffffffffu, h2_as_u32(s[r]), M);
        unsigned o2 = __shfl_xor_sync(0xffffffffu, h2_as_u32(t[r]), M);
        __half2 v1 = u32_as_h2(o1);
        __half2 v2 = u32_as_h2(o2);
        s[r] = keepmin ? __hmin2(s[r], v1) : __hmax2(s[r], v1);
        t[r] = keepmin ? __hmin2(t[r], v2) : __hmax2(t[r], v2);
    }
}
__device__ __forceinline__ void sort256x2h(__half2 s[8], __half2 t[8], int lane) {
    int b0 = lane & 1, b1 = (lane >> 1) & 1, b2 = (lane >> 2) & 1;
    int b3 = (lane >> 3) & 1, b4 = (lane >> 4) & 1;
    bool k1 = (lane & 1) == 0, k2 = (lane & 2) == 0, k4 = (lane & 4) == 0;
    bool k8 = (lane & 8) == 0, k16 = (lane & 16) == 0;
    negif2h(s, t, b0);
    batcher8x2h(s, t);
    negif2h(s, t, b0 ^ b1);
    shufstage2h<1>(s, t, k1);
    inreg3x2h(s, t);
    negif2h(s, t, b1 ^ b2);
    shufstage2h<2>(s, t, k2);
    shufstage2h<1>(s, t, k1);
    inreg3x2h(s, t);
    negif2h(s, t, b2 ^ b3);
    shufstage2h<4>(s, t, k4);
    shufstage2h<2>(s, t, k2);
    shufstage2h<1>(s, t, k1);
    inreg3x2h(s, t);
    negif2h(s, t, b3 ^ b4);
    shufstage2h<8>(s, t, k8);
    shufstage2h<4>(s, t, k4);
    shufstage2h<2>(s, t, k2);
    shufstage2h<1>(s, t, k1);
    inreg3x2h(s, t);
    negif2h(s, t, b4);
    shufstage2h<16>(s, t, k16);
    shufstage2h<8>(s, t, k8);
    shufstage2h<4>(s, t, k4);
    shufstage2h<2>(s, t, k2);
    shufstage2h<1>(s, t, k1);
    inreg3x2h(s, t);
}

// ---------------------------------------------------------------------------
// Fused branch (separate kernel per S to keep per-SM instruction footprint
// small): taps broadcast-half2, products in hfma2, packed sort, fp32 epilogue;
// output packed half (one 16B store per lane). Reads g_c plane `br`.
template <int S>
__global__ void __launch_bounds__(256, 3) fused_branch(int br) {
    constexpr int NC = 8 + 2 * S;           // columns in tile
    constexpr int CP = 289;
    __shared__ float cs[NC * CP];
    __shared__ __half2 k3h[64];             // [pair p][d] = {k3[2p][d], k3[2p+1][d]}
    __shared__ float k4s[16];

    int b = blockIdx.z, g = blockIdx.y, w0 = blockIdx.x * 8;
    int tid  = threadIdx.x;
    int lane = tid & 31, warp = tid >> 5;

    if (tid < 64) {
        int p = tid >> 3, d = tid & 7;
        int row = g * 16 + 2 * p;
        k3h[tid] = __floats2half2_rn(g_k3[row * 8 + d], g_k3[(row + 1) * 8 + d]);
    }
    if (tid < 16) k4s[tid] = g_k4[g * 16 + tid];

    const float* cbase = g_c + (size_t)br * (4 * 16 * HW)
                       + (size_t)(b * 16 + g) * HW;
    #pragma unroll 1
    for (int j = tid; j < NC * 256; j += 256) {
        int h   = j / NC;
        int col = j - h * NC;
        int wg  = w0 - S + col;
        float v = 0.f;
        if ((unsigned)wg < 256u) v = cbase[h * 256 + wg];
        cs[col * CP + h + (h >> 3)] = v;
    }
    __syncthreads();

    int colc = warp + S;
    const float* pC = cs + colc * CP;
    const float* pL = cs + (colc - S) * CP;
    const float* pR = cs + (colc + S) * CP;

    __half2 Lh[8], Ch[8], Rh[8];
    float acc[8];
    #pragma unroll
    for (int r = 0; r < 8; ++r) {
        int h  = lane * 8 + r;
        int ai = h + (h >> 3);
        Lh[r] = __float2half2_rn(pL[ai]);
        Ch[r] = __float2half2_rn(pC[ai]);
        Rh[r] = __float2half2_rn(pR[ai]);
        acc[r] = 0.f;
    }

    #pragma unroll 1
    for (int ep = 0; ep < 4; ++ep) {
        __half2 whA[8], whB[8];
        #pragma unroll
        for (int d = 0; d < 8; ++d) {
            whA[d] = k3h[(2 * ep)     * 8 + d];
            whB[d] = k3h[(2 * ep + 1) * 8 + d];
        }

        __half2 s[8], t[8];
        #pragma unroll
        for (int r = 0; r < 8; ++r) {
            __half2 luh, cuh, ruh, ldh, cdh, rdh;
            if (r >= S) {
                luh = Lh[r - S]; cuh = Ch[r - S]; ruh = Rh[r - S];
            } else {
                int hm  = lane * 8 + r - S;
                bool vm = hm >= 0;
                int hmc = vm ? hm : 0;
                int aim = hmc + (hmc >> 3);
                luh = __float2half2_rn(vm ? pL[aim] : 0.f);
                cuh = __float2half2_rn(vm ? pC[aim] : 0.f);
                ruh = __float2half2_rn(vm ? pR[aim] : 0.f);
            }
            if (r + S < 8) {
                ldh = Lh[r + S]; cdh = Ch[r + S]; rdh = Rh[r + S];
            } else {
                int hp  = lane * 8 + r + S;
                bool vp = hp < 256;
                int hpc = vp ? hp : 255;
                int aip = hpc + (hpc >> 3);
                ldh = __float2half2_rn(vp ? pL[aip] : 0.f);
                cdh = __float2half2_rn(vp ? pC[aip] : 0.f);
                rdh = __float2half2_rn(vp ? pR[aip] : 0.f);
            }
            __half2 cch = Ch[r], Lrh = Lh[r], Rrh = Rh[r];

            __half2 A0 = __hmul2(luh, whA[0]);
            A0 = __hfma2(cuh, whA[1], A0); A0 = __hfma2(ruh, whA[2], A0);
            A0 = __hfma2(Lrh, whA[3], A0); A0 = __hfma2(rdh, whA[4], A0);
            A0 = __hfma2(cdh, whA[5], A0); A0 = __hfma2(ldh, whA[6], A0);
            A0 = __hfma2(Rrh, whA[7], A0);
            __half2 B0 = __hmul2(rdh, whA[0]);
            B0 = __hfma2(cdh, whA[1], B0); B0 = __hfma2(ldh, whA[2], B0);
            B0 = __hfma2(Rrh, whA[3], B0); B0 = __hfma2(luh, whA[4], B0);
            B0 = __hfma2(cuh, whA[5], B0); B0 = __hfma2(ruh, whA[6], B0);
            B0 = __hfma2(Lrh, whA[7], B0);
            s[r] = __hmul2(__hsub2(cch, A0), __hsub2(cch, B0));

            __half2 A1 = __hmul2(luh, whB[0]);
            A1 = __hfma2(cuh, whB[1], A1); A1 = __hfma2(ruh, whB[2], A1);
            A1 = __hfma2(Lrh, whB[3], A1); A1 = __hfma2(rdh, whB[4], A1);
            A1 = __hfma2(cdh, whB[5], A1); A1 = __hfma2(ldh, whB[6], A1);
            A1 = __hfma2(Rrh, whB[7], A1);
            __half2 B1 = __hmul2(rdh, whB[0]);
            B1 = __hfma2(cdh, whB[1], B1); B1 = __hfma2(ldh, whB[2], B1);
            B1 = __hfma2(Rrh, whB[3], B1); B1 = __hfma2(luh, whB[4], B1);
            B1 = __hfma2(cuh, whB[5], B1); B1 = __hfma2(ruh, whB[6], B1);
            B1 = __hfma2(Lrh, whB[7], B1);
            t[r] = __hmul2(__hsub2(cch, A1), __hsub2(cch, B1));
        }

        sort256x2h(s, t, lane);

        int e0 = 4 * ep;
        float k40 = k4s[e0 + 0], k41 = k4s[e0 + 1];
        float k42 = k4s[e0 + 2], k43 = k4s[e0 + 3];
        #pragma unroll
        for (int r = 0; r < 8; ++r) {
            float v0 = __low2float(s[r]),  v1 = __high2float(s[r]);
            float v2 = __low2float(t[r]),  v3 = __high2float(t[r]);
            float g0 = 1.f / (1.f + __expf(-v0));
            float g1 = 1.f / (1.f + __expf(-v1));
            float g2 = 1.f / (1.f + __expf(-v2));
            float g3 = 1.f / (1.f + __expf(-v3));
            float a = acc[r];
            a = fmaf(k40 * v0, g0, a);
            a = fmaf(k41 * v1, g1, a);
            a = fmaf(k42 * v2, g2, a);
            a = fmaf(k43 * v3, g3, a);
            acc[r] = a;
        }
    }

    int w = w0 + warp;
    __half* op = g_brh + (size_t)br * BRS + ((size_t)((b * 16 + g) * 256 + w)) * 256;
    __half2 o[4];
    o[0] = __floats2half2_rn(acc[0], acc[1]);
    o[1] = __floats2half2_rn(acc[2], acc[3]);
    o[2] = __floats2half2_rn(acc[4], acc[5]);
    o[3] = __floats2half2_rn(acc[6], acc[7]);
    *reinterpret_cast<uint4*>(op + lane * 8) = *reinterpret_cast<uint4*>(o);
}

// ---------------------------------------------------------------------------
// 3x3 conv on transposed layout with on-the-fly branch combine (max + mean of
// 4 half branch planes) + BN(eval) + SiLU + 1x1 -> sigmoid mask.
__global__ void post_conv(const float* __restrict__ wb,
                          const float* __restrict__ gamma,
                          const float* __restrict__ beta,
                          const float* __restrict__ mean,
                          const float* __restrict__ var,
                          const float* __restrict__ wout,
                          const float* __restrict__ bout) {
    __shared__ float tile[18][35];
    __shared__ float ws[16 * 9];
    int b  = blockIdx.z;
    int o0 = blockIdx.y * 16, i0 = blockIdx.x * 32;
    int tx = threadIdx.x, ty = threadIdx.y;
    int tid = ty * 32 + tx;
    float acc[16][2];
    #pragma unroll
    for (int co = 0; co < 16; ++co) { acc[co][0] = 0.f; acc[co][1] = 0.f; }
    for (int ci = 0; ci < 16; ++ci) {
        __syncthreads();
        for (int i = tid; i < 144; i += 256) {
            int co = i / 9, rc = i % 9;
            int bi = rc / 3, ao = rc % 3;
            ws[co * 9 + ao * 3 + bi] = wb[(co * 16 + ci) * 9 + bi * 3 + ao];
        }
        size_t plane = (size_t)(b * 16 + ci) * HW;
        for (int i = tid; i < 18 * 34; i += 256) {
            int to = i / 34, ti = i - to * 34;
            int oo = o0 + to - 1, ii = i0 + ti - 1;
            float v = 0.f;
            if ((unsigned)oo < 256u && (unsigned)ii < 256u) {
                size_t off = plane + oo * 256 + ii;
                float v0 = __half2float(g_brh[off]);
                float v1 = __half2float(g_brh[BRS + off]);
                float v2 = __half2float(g_brh[2 * (size_t)BRS + off]);
                float v3 = __half2float(g_brh[3 * (size_t)BRS + off]);
                v = fmaxf(fmaxf(v0, v1), fmaxf(v2, v3))
                    + 0.25f * (v0 + v1 + v2 + v3);
            }
            tile[to][ti] = v;
        }
        __syncthreads();
        #pragma unroll
        for (int a = 0; a < 3; ++a)
            #pragma unroll
            for (int bb = 0; bb < 3; ++bb) {
                float v0 = tile[ty + a][tx + bb];
                float v1 = tile[ty + 8 + a][tx + bb];
                #pragma unroll
                for (int co = 0; co < 16; ++co) {
                    float wv = ws[co * 9 + a * 3 + bb];
                    acc[co][0] = fmaf(wv, v0, acc[co][0]);
                    acc[co][1] = fmaf(wv, v1, acc[co][1]);
                }
            }
    }
    float m0 = 0.f, m1 = 0.f;
    #pragma unroll
    for (int co = 0; co < 16; ++co) {
        float sc = __ldg(gamma + co) * rsqrtf(__ldg(var + co) + 1e-5f);
        float sh = __ldg(beta + co) - __ldg(mean + co) * sc;
        float h0 = acc[co][0] * sc + sh;
        float h1 = acc[co][1] * sc + sh;
        h0 = h0 / (1.f + __expf(-h0));
        h1 = h1 / (1.f + __expf(-h1));
        float wv = __ldg(wout + co);
        m0 = fmaf(wv, h0, m0);
        m1 = fmaf(wv, h1, m1);
    }
    float bo = __ldg(bout);
    m0 = 1.f / (1.f + __expf(-(m0 + bo)));
    m1 = 1.f / (1.f + __expf(-(m1 + bo)));
    float* mp = g_mask + (size_t)b * HW + (o0 + ty) * 256 + i0 + tx;
    mp[0]       = m0;
    mp[8 * 256] = m1;
}

// ---------------------------------------------------------------------------
// Final: out = cen * (mask*m*s0 + m*s1 + s2*mask + s3), mask stored [b][w][h].
__global__ void final_kernel(const float* __restrict__ cen,
                             const float* __restrict__ mas,
                             float* __restrict__ out) {
    __shared__ float mt[1024];              // [w][hoff] for this block's 4 rows
    int b  = blockIdx.y;
    int h0 = blockIdx.x * 4;
    int tid = threadIdx.x;
    #pragma unroll
    for (int i = tid; i < 1024; i += 256) {
        int wv = i >> 2, hoff = i & 3;
        mt[i] = g_mask[(size_t)b * HW + wv * 256 + h0 + hoff];
    }
    __syncthreads();
    float s0 = g_s1[0], s1 = g_s1[1], s2 = g_s1[2], s3 = g_s1[3];
    int hoff = tid >> 6;
    int h    = h0 + hoff;
    int wb4  = (tid & 63) * 4;
    float4 msv = *reinterpret_cast<const float4*>(
        mas + (size_t)b * HW + h * 256 + wb4);
    float coef[4];
    {
        float msa[4] = {msv.x, msv.y, msv.z, msv.w};
        #pragma unroll
        for (int j = 0; j < 4; ++j) {
            float mv = mt[(wb4 + j) * 4 + hoff];
            float m  = 1.f / (1.f + __expf(-msa[j]));
            coef[j] = m * fmaf(mv, s0, s1) + fmaf(s2, mv, s3);
        }
    }
    size_t base = (size_t)b * 64 * HW + (size_t)h * 256 + wb4;
    #pragma unroll 4
    for (int c = 0; c < 64; ++c) {
        size_t o = base + (size_t)c * HW;
        float4 cv = *reinterpret_cast<const float4*>(cen + o);
        cv.x *= coef[0]; cv.y *= coef[1]; cv.z *= coef[2]; cv.w *= coef[3];
        *reinterpret_cast<float4*>(out + o) = cv;
    }
}

// ---------------------------------------------------------------------------
extern "C" void kernel_launch(void* const* d_in, const int* in_sizes, int n_in,
                              void* d_out, int out_size) {
    const float* cen      = (const float*)d_in[0];
    const float* mas      = (const float*)d_in[1];
    const float* w_in     = (const float*)d_in[2];
    const float* b_in     = (const float*)d_in[3];
    const float* w_c0     = (const float*)d_in[4];
    const float* b_c0     = (const float*)d_in[5];
    const float* w_c1     = (const float*)d_in[6];
    const float* b_c1     = (const float*)d_in[7];
    const float* w_c2     = (const float*)d_in[8];
    const float* b_c2     = (const float*)d_in[9];
    const float* w_c3     = (const float*)d_in[10];
    const float* b_c3     = (const float*)d_in[11];
    const float* scales1  = (const float*)d_in[12];
    const float* scales2  = (const float*)d_in[13];
    const float* scales3  = (const float*)d_in[14];
    const float* w_base   = (const float*)d_in[15];
    const float* bn_gamma = (const float*)d_in[16];
    const float* bn_beta  = (const float*)d_in[17];
    const float* bn_mean  = (const float*)d_in[18];
    const float* bn_var   = (const float*)d_in[19];
    const float* w_out    = (const float*)d_in[20];
    const float* b_out    = (const float*)d_in[21];
    float* out = (float*)d_out;

    prep_kernel<<<1, 256>>>(scales1, scales2, scales3);
    in_conv<<<1024, 256>>>(cen, w_in, b_in);

    mid_all<<<dim3(32, 16, 4), 256>>>(w_c0, b_c0, w_c1, b_c1,
                                      w_c2, b_c2, w_c3, b_c3);

    dim3 fgrid(32, 16, 4);
    fused_branch<1><<<fgrid, 256>>>(0);
    fused_branch<3><<<fgrid, 256>>>(1);
    fused_branch<5><<<fgrid, 256>>>(2);
    fused_branch<7><<<fgrid, 256>>>(3);

    dim3 cgrid(8, 16, 4), cblk(32, 8);
    post_conv<<<cgrid, cblk>>>(w_base, bn_gamma, bn_beta, bn_mean, bn_var,
                               w_out, b_out);

    final_kernel<<<dim3(64, 4), 256>>>(cen, mas, out);
}